// round 4
// baseline (speedup 1.0000x reference)
#include <cuda_runtime.h>
#include <math.h>

// B=32, N=4096, D=512, K=64
#define Bb 32
#define Nn 4096
#define Dd 512
#define Kk 64

typedef unsigned long long ull;

__device__ float g_assign[(size_t)Bb * Nn * Kk];   // softmax assignments [b,n,k]
__device__ float g_vlad[(size_t)Bb * Kk * Dd];     // raw vlad, stored [b,k,d]
__device__ float g_asum[Bb * Kk];
__device__ float g_gnormsq[Bb];

// ---- packed f32x2 helpers -------------------------------------------------
__device__ __forceinline__ ull dup2(float x) {
    ull r; asm("mov.b64 %0, {%1, %1};" : "=l"(r) : "f"(x)); return r;
}
__device__ __forceinline__ void fma2(ull& d, ull a, ull b) {
    asm("fma.rn.f32x2 %0, %1, %2, %0;" : "+l"(d) : "l"(a), "l"(b));
}
__device__ __forceinline__ void unpk(ull v, float& lo, float& hi) {
    asm("mov.b64 {%0, %1}, %2;" : "=f"(lo), "=f"(hi) : "l"(v));
}

// ---------------------------------------------------------------------------
__global__ void k0_init() {
    int i = blockIdx.x * 256 + threadIdx.x;
    if (i < Bb * Kk) g_asum[i] = 0.0f;
    if (i < Bb)      g_gnormsq[i] = 0.0f;
}

// ---------------------------------------------------------------------------
// k1: logits GEMM (131072x512 @ 512x64) + BN + softmax + assignment + a_sum.
// Block: 256 rows x 64 cols, 256 threads, 8x8 per thread, FFMA2 packed along
// row pairs. x tile stored TRANSPOSED in smem: xs[d][row].
// ---------------------------------------------------------------------------
__global__ __launch_bounds__(256) void k1_logits_softmax(
    const float* __restrict__ x,
    const float* __restrict__ clusters,
    const float* __restrict__ bnw,
    const float* __restrict__ bnb,
    const float* __restrict__ rm,
    const float* __restrict__ rv)
{
    __shared__ float xs[2][16][260];   // [buf][d within chunk][row], stride 260
    __shared__ float cs[2][16][68];    // [buf][d][k]
    __shared__ float red[8 * 64];

    const int tid  = threadIdx.x;
    const int row0 = blockIdx.x * 256;
    const int ty = tid >> 3;          // 0..31 : rows ty*8 .. ty*8+7
    const int tx = tid & 7;           // 0..7  : cols tx*8 .. tx*8+7

    // loader mapping for x: thread -> (64-row group, 16B column seg)
    const int lr = tid >> 2;          // 0..63
    const int lc = (tid & 3) * 4;     // 0,4,8,12 (within 16-wide d chunk)
    // loader mapping for clusters
    const int cr = tid >> 4;          // 0..15
    const int cc = (tid & 15) * 4;    // 0..60

    const float* xg = x + (size_t)row0 * Dd;

    ull acc[4][8];
#pragma unroll
    for (int i = 0; i < 4; i++)
#pragma unroll
        for (int j = 0; j < 8; j++) acc[i][j] = 0ull;

    float4 px[4];
    float4 pc;

    // prefetch chunk 0
#pragma unroll
    for (int p = 0; p < 4; p++)
        px[p] = *(const float4*)&xg[(size_t)(lr + p * 64) * Dd + lc];
    pc = *(const float4*)&clusters[(size_t)cr * Kk + cc];

    for (int c = 0; c < 32; c++) {
        const int buf = c & 1;
        // store prefetched chunk (x transposed)
#pragma unroll
        for (int p = 0; p < 4; p++) {
            int r = lr + p * 64;
            xs[buf][lc + 0][r] = px[p].x;
            xs[buf][lc + 1][r] = px[p].y;
            xs[buf][lc + 2][r] = px[p].z;
            xs[buf][lc + 3][r] = px[p].w;
        }
        *(float4*)&cs[buf][cr][cc] = pc;
        __syncthreads();

        if (c < 31) {
            int d0 = (c + 1) * 16;
#pragma unroll
            for (int p = 0; p < 4; p++)
                px[p] = *(const float4*)&xg[(size_t)(lr + p * 64) * Dd + d0 + lc];
            pc = *(const float4*)&clusters[(size_t)(d0 + cr) * Kk + cc];
        }

#pragma unroll
        for (int kk = 0; kk < 16; kk++) {
            ulonglong2 a01 = *(ulonglong2*)&xs[buf][kk][ty * 8];
            ulonglong2 a23 = *(ulonglong2*)&xs[buf][kk][ty * 8 + 4];
            float4 b0 = *(float4*)&cs[buf][kk][tx * 8];
            float4 b1 = *(float4*)&cs[buf][kk][tx * 8 + 4];
            ull d0 = dup2(b0.x), d1 = dup2(b0.y), d2 = dup2(b0.z), d3 = dup2(b0.w);
            ull d4 = dup2(b1.x), d5 = dup2(b1.y), d6 = dup2(b1.z), d7 = dup2(b1.w);
            fma2(acc[0][0], a01.x, d0); fma2(acc[0][1], a01.x, d1);
            fma2(acc[0][2], a01.x, d2); fma2(acc[0][3], a01.x, d3);
            fma2(acc[0][4], a01.x, d4); fma2(acc[0][5], a01.x, d5);
            fma2(acc[0][6], a01.x, d6); fma2(acc[0][7], a01.x, d7);
            fma2(acc[1][0], a01.y, d0); fma2(acc[1][1], a01.y, d1);
            fma2(acc[1][2], a01.y, d2); fma2(acc[1][3], a01.y, d3);
            fma2(acc[1][4], a01.y, d4); fma2(acc[1][5], a01.y, d5);
            fma2(acc[1][6], a01.y, d6); fma2(acc[1][7], a01.y, d7);
            fma2(acc[2][0], a23.x, d0); fma2(acc[2][1], a23.x, d1);
            fma2(acc[2][2], a23.x, d2); fma2(acc[2][3], a23.x, d3);
            fma2(acc[2][4], a23.x, d4); fma2(acc[2][5], a23.x, d5);
            fma2(acc[2][6], a23.x, d6); fma2(acc[2][7], a23.x, d7);
            fma2(acc[3][0], a23.y, d0); fma2(acc[3][1], a23.y, d1);
            fma2(acc[3][2], a23.y, d2); fma2(acc[3][3], a23.y, d3);
            fma2(acc[3][4], a23.y, d4); fma2(acc[3][5], a23.y, d5);
            fma2(acc[3][6], a23.y, d6); fma2(acc[3][7], a23.y, d7);
        }
        __syncthreads();
    }

    // ---- epilogue: BN + softmax (rows ty*8..+7, cols tx*8..+7) ----
    float sc[8], sh[8];
#pragma unroll
    for (int j = 0; j < 8; j++) {
        int k = tx * 8 + j;
        float istd = rsqrtf(rv[k] + 1e-5f);
        sc[j] = bnw[k] * istd;
        sh[j] = bnb[k] - rm[k] * sc[j];
    }

    float colsum[8];
#pragma unroll
    for (int j = 0; j < 8; j++) colsum[j] = 0.0f;

    float* ag = g_assign + (size_t)row0 * Kk;

#pragma unroll
    for (int i2 = 0; i2 < 4; i2++) {
        float r0[8], r1[8];
#pragma unroll
        for (int j = 0; j < 8; j++) {
            float lo, hi; unpk(acc[i2][j], lo, hi);
            r0[j] = lo * sc[j] + sh[j];
            r1[j] = hi * sc[j] + sh[j];
        }
#pragma unroll
        for (int half = 0; half < 2; half++) {
            float* r = half ? r1 : r0;
            int row = ty * 8 + i2 * 2 + half;
            float m = r[0];
#pragma unroll
            for (int j = 1; j < 8; j++) m = fmaxf(m, r[j]);
            m = fmaxf(m, __shfl_xor_sync(0xffffffffu, m, 1));
            m = fmaxf(m, __shfl_xor_sync(0xffffffffu, m, 2));
            m = fmaxf(m, __shfl_xor_sync(0xffffffffu, m, 4));
            float s = 0.0f;
#pragma unroll
            for (int j = 0; j < 8; j++) { r[j] = __expf(r[j] - m); s += r[j]; }
            s += __shfl_xor_sync(0xffffffffu, s, 1);
            s += __shfl_xor_sync(0xffffffffu, s, 2);
            s += __shfl_xor_sync(0xffffffffu, s, 4);
            float inv = 1.0f / s;
#pragma unroll
            for (int j = 0; j < 8; j++) { r[j] *= inv; colsum[j] += r[j]; }
            float4 w0 = make_float4(r[0], r[1], r[2], r[3]);
            float4 w1 = make_float4(r[4], r[5], r[6], r[7]);
            *(float4*)&ag[(size_t)row * Kk + tx * 8]     = w0;
            *(float4*)&ag[(size_t)row * Kk + tx * 8 + 4] = w1;
        }
    }

    // reduce colsum over ty groups within warp (lanes differing in bits 3,4)
#pragma unroll
    for (int j = 0; j < 8; j++) {
        colsum[j] += __shfl_xor_sync(0xffffffffu, colsum[j], 8);
        colsum[j] += __shfl_xor_sync(0xffffffffu, colsum[j], 16);
    }
    int lane = tid & 31;
    int wrp = tid >> 5;
    if (lane < 8) {
#pragma unroll
        for (int j = 0; j < 8; j++)
            red[wrp * 64 + lane * 8 + j] = colsum[j];
    }
    __syncthreads();
    if (tid < 64) {
        float s = 0.0f;
#pragma unroll
        for (int w = 0; w < 8; w++) s += red[w * 64 + tid];
        atomicAdd(&g_asum[(row0 >> 12) * Kk + tid], s);
    }
}

// ---------------------------------------------------------------------------
// k2: per-batch vlad[b,d,k] = sum_n assign[b,n,k] * x[b,n,d].
// Block: (b, 64-wide d tile), 128 threads, 8d x 4k per thread, FFMA2 packed
// along d pairs. grid = (8, 32) = 256 blocks. Output stored [b,k,d].
// ---------------------------------------------------------------------------
__global__ __launch_bounds__(128) void k2_vlad(const float* __restrict__ x)
{
    __shared__ float xs[2][32][68];   // [buf][n][d] (64 d + pad)
    __shared__ float as[2][32][68];   // [buf][n][k]

    const int tid = threadIdx.x;
    const int b  = blockIdx.y;
    const int d0 = blockIdx.x * 64;
    const int td = tid & 7;           // 8 d-groups x 8d
    const int tk = tid >> 3;          // 16 k-groups x 4k

    const int lr = tid >> 2;          // 0..31 (n row within chunk)
    const int lc = (tid & 3) * 16;    // 0,16,32,48

    const float* xg = x + (size_t)b * Nn * Dd + d0;
    const float* ag = g_assign + (size_t)b * Nn * Kk;

    ull acc[4][4];
#pragma unroll
    for (int i = 0; i < 4; i++)
#pragma unroll
        for (int j = 0; j < 4; j++) acc[i][j] = 0ull;

    float4 px[4], pa[4];
#pragma unroll
    for (int q = 0; q < 4; q++) {
        px[q] = *(const float4*)&xg[(size_t)lr * Dd + lc + q * 4];
        pa[q] = *(const float4*)&ag[(size_t)lr * Kk + lc + q * 4];
    }

    for (int c = 0; c < 128; c++) {
        const int buf = c & 1;
#pragma unroll
        for (int q = 0; q < 4; q++) {
            *(float4*)&xs[buf][lr][lc + q * 4] = px[q];
            *(float4*)&as[buf][lr][lc + q * 4] = pa[q];
        }
        __syncthreads();

        if (c < 127) {
            int n0 = (c + 1) * 32;
#pragma unroll
            for (int q = 0; q < 4; q++) {
                px[q] = *(const float4*)&xg[(size_t)(n0 + lr) * Dd + lc + q * 4];
                pa[q] = *(const float4*)&ag[(size_t)(n0 + lr) * Kk + lc + q * 4];
            }
        }

#pragma unroll 8
        for (int kk = 0; kk < 32; kk++) {
            ulonglong2 aA = *(ulonglong2*)&xs[buf][kk][td * 8];
            ulonglong2 aB = *(ulonglong2*)&xs[buf][kk][td * 8 + 4];
            float4 bv = *(float4*)&as[buf][kk][tk * 4];
            ull db0 = dup2(bv.x), db1 = dup2(bv.y), db2 = dup2(bv.z), db3 = dup2(bv.w);
            fma2(acc[0][0], aA.x, db0); fma2(acc[0][1], aA.x, db1);
            fma2(acc[0][2], aA.x, db2); fma2(acc[0][3], aA.x, db3);
            fma2(acc[1][0], aA.y, db0); fma2(acc[1][1], aA.y, db1);
            fma2(acc[1][2], aA.y, db2); fma2(acc[1][3], aA.y, db3);
            fma2(acc[2][0], aB.x, db0); fma2(acc[2][1], aB.x, db1);
            fma2(acc[2][2], aB.x, db2); fma2(acc[2][3], aB.x, db3);
            fma2(acc[3][0], aB.y, db0); fma2(acc[3][1], aB.y, db1);
            fma2(acc[3][2], aB.y, db2); fma2(acc[3][3], aB.y, db3);
        }
        __syncthreads();
    }

    // epilogue: write [b][k][d] (8 consecutive d per k)
#pragma unroll
    for (int j = 0; j < 4; j++) {
        float v[8];
#pragma unroll
        for (int p = 0; p < 4; p++) unpk(acc[p][j], v[2 * p], v[2 * p + 1]);
        float* o = &g_vlad[((size_t)b * Kk + tk * 4 + j) * Dd + d0 + td * 8];
        *(float4*)&o[0] = make_float4(v[0], v[1], v[2], v[3]);
        *(float4*)&o[4] = make_float4(v[4], v[5], v[6], v[7]);
    }
}

// ---------------------------------------------------------------------------
// k3: subtract a_sum*clusters2, intra-normalize over D, accumulate global sumsq
// ---------------------------------------------------------------------------
__global__ __launch_bounds__(128) void k3_colnorm(const float* __restrict__ c2,
                                                  float* __restrict__ out)
{
    const int bk = blockIdx.x;
    const int b = bk >> 6;
    const int k = bk & 63;
    const int tid = threadIdx.x;

    const float a = g_asum[bk];
    const float* vr = g_vlad + (size_t)bk * Dd;

    float v[4];
    float ss = 0.0f;
#pragma unroll
    for (int p = 0; p < 4; p++) {
        int d = tid + p * 128;
        float t = vr[d] - a * c2[(size_t)d * Kk + k];
        v[p] = t;
        ss += t * t;
    }
#pragma unroll
    for (int o = 16; o; o >>= 1) ss += __shfl_xor_sync(0xffffffffu, ss, o);

    __shared__ float sred[4];
    if ((tid & 31) == 0) sred[tid >> 5] = ss;
    __syncthreads();
    float tot = sred[0] + sred[1] + sred[2] + sred[3];
    float inv = 1.0f / fmaxf(sqrtf(tot), 1e-12f);
    if (tid == 0) atomicAdd(&g_gnormsq[b], tot * inv * inv);

    float* ob = out + (size_t)b * (Dd * Kk);
#pragma unroll
    for (int p = 0; p < 4; p++) {
        int d = tid + p * 128;
        ob[(size_t)d * Kk + k] = v[p] * inv;
    }
}

// ---------------------------------------------------------------------------
__global__ void k4_scale(float* __restrict__ out)
{
    int idx = blockIdx.x * 256 + threadIdx.x;
    int b = idx >> 15;
    out[idx] *= 1.0f / fmaxf(sqrtf(g_gnormsq[b]), 1e-12f);
}

// ---------------------------------------------------------------------------
extern "C" void kernel_launch(void* const* d_in, const int* in_sizes, int n_in,
                              void* d_out, int out_size)
{
    const float* x        = (const float*)d_in[0];
    const float* clusters = (const float*)d_in[1];
    const float* c2       = (const float*)d_in[2];
    const float* bnw      = (const float*)d_in[3];
    const float* bnb      = (const float*)d_in[4];
    const float* rm       = (const float*)d_in[5];
    const float* rv       = (const float*)d_in[6];
    float* out = (float*)d_out;

    k0_init<<<8, 256>>>();
    k1_logits_softmax<<<(Bb * Nn) / 256, 256>>>(x, clusters, bnw, bnb, rm, rv);
    dim3 g2(Dd / 64, Bb);
    k2_vlad<<<g2, 128>>>(x);
    k3_colnorm<<<Bb * Kk, 128>>>(c2, out);
    k4_scale<<<(Bb * Dd * Kk) / 256, 256>>>(out);
}

// round 5
// speedup vs baseline: 1.9408x; 1.9408x over previous
#include <cuda_runtime.h>
#include <math.h>
#include <stdint.h>

// B=32, N=4096, D=512, K=64
#define Bb 32
#define Nn 4096
#define Dd 512
#define Kk 64

__device__ float g_assign[(size_t)Bb * Nn * Kk];   // softmax assignments [b,n,k]
__device__ float g_vlad[(size_t)Bb * Kk * Dd];     // raw vlad, stored [b,k,d]
__device__ float g_asum[Bb * Kk];
__device__ float g_gnormsq[Bb];

// ---- tf32 helpers ----------------------------------------------------------
__device__ __forceinline__ uint32_t tf32b(float f) {
    uint32_t u; asm("cvt.rna.tf32.f32 %0, %1;" : "=r"(u) : "f"(f)); return u;
}
__device__ __forceinline__ float tf32f(float f) { return __uint_as_float(tf32b(f)); }

__device__ __forceinline__ void mma8(float* c, uint32_t a0, uint32_t a1,
                                     uint32_t a2, uint32_t a3,
                                     uint32_t b0, uint32_t b1) {
    asm volatile(
        "mma.sync.aligned.m16n8k8.row.col.f32.tf32.tf32.f32 "
        "{%0,%1,%2,%3},{%4,%5,%6,%7},{%8,%9},{%0,%1,%2,%3};\n"
        : "+f"(c[0]), "+f"(c[1]), "+f"(c[2]), "+f"(c[3])
        : "r"(a0), "r"(a1), "r"(a2), "r"(a3), "r"(b0), "r"(b1));
}

// ---------------------------------------------------------------------------
__global__ void k0_init() {
    int i = blockIdx.x * 256 + threadIdx.x;
    if (i < Bb * Kk) g_asum[i] = 0.0f;
    if (i < Bb)      g_gnormsq[i] = 0.0f;
}

// ---------------------------------------------------------------------------
// k1: logits = x @ clusters (131072x512 @ 512x64) via tf32 MMA, fused
// BN(eval) + softmax + assignment store + a_sum atomic.
// Block: 256 thr (8 warps), tile 128 rows x 64 cols, K chunk 32.
// Warp w owns rows w*16..w*16+15, all 64 cols (8 n-tiles of m16n8k8).
// ---------------------------------------------------------------------------
__global__ __launch_bounds__(256) void k1_logits_softmax(
    const float* __restrict__ x,
    const float* __restrict__ clusters,
    const float* __restrict__ bnw,
    const float* __restrict__ bnb,
    const float* __restrict__ rm,
    const float* __restrict__ rv)
{
    __shared__ float xs[128][36];   // x chunk [row][k], bank = row*4+k (perfect)
    __shared__ float cs[32][72];    // clusters chunk [k][n], bank = k*8+n (perfect)
    __shared__ float scf[64], shf[64];
    __shared__ float red[8 * 64];

    const int tid  = threadIdx.x;
    const int lane = tid & 31;
    const int w    = tid >> 5;
    const int la   = lane >> 2;     // 0..7
    const int lb   = lane & 3;      // 0..3
    const int row0 = blockIdx.x * 128;

    // loader mappings
    const int xr = tid >> 1;              // 0..127
    const int xc = (tid & 1) * 16;        // 0 or 16
    const int cr = tid >> 3;              // 0..31
    const int cc = (tid & 7) * 8;         // 0..56

    const float* xg = x + (size_t)row0 * Dd;

    float acc[8][4];
#pragma unroll
    for (int j = 0; j < 8; j++)
#pragma unroll
        for (int q = 0; q < 4; q++) acc[j][q] = 0.0f;

    float4 px[4];
    float4 pc[2];
#pragma unroll
    for (int q = 0; q < 4; q++)
        px[q] = *(const float4*)&xg[(size_t)xr * Dd + xc + q * 4];
#pragma unroll
    for (int q = 0; q < 2; q++)
        pc[q] = *(const float4*)&clusters[(size_t)cr * Kk + cc + q * 4];

    for (int c = 0; c < 16; c++) {
        // store prefetched chunk (convert to tf32 bits)
#pragma unroll
        for (int q = 0; q < 4; q++) {
            float4 t = make_float4(tf32f(px[q].x), tf32f(px[q].y),
                                   tf32f(px[q].z), tf32f(px[q].w));
            *(float4*)&xs[xr][xc + q * 4] = t;
        }
#pragma unroll
        for (int q = 0; q < 2; q++) {
            float4 t = make_float4(tf32f(pc[q].x), tf32f(pc[q].y),
                                   tf32f(pc[q].z), tf32f(pc[q].w));
            *(float4*)&cs[cr][cc + q * 4] = t;
        }
        __syncthreads();

        if (c < 15) {
            int d0 = (c + 1) * 32;
#pragma unroll
            for (int q = 0; q < 4; q++)
                px[q] = *(const float4*)&xg[(size_t)xr * Dd + d0 + xc + q * 4];
#pragma unroll
            for (int q = 0; q < 2; q++)
                pc[q] = *(const float4*)&clusters[(size_t)(d0 + cr) * Kk + cc + q * 4];
        }

        const int wr = w * 16 + la;
#pragma unroll
        for (int kk = 0; kk < 4; kk++) {
            uint32_t a0 = __float_as_uint(xs[wr][kk * 8 + lb]);
            uint32_t a1 = __float_as_uint(xs[wr + 8][kk * 8 + lb]);
            uint32_t a2 = __float_as_uint(xs[wr][kk * 8 + 4 + lb]);
            uint32_t a3 = __float_as_uint(xs[wr + 8][kk * 8 + 4 + lb]);
#pragma unroll
            for (int j = 0; j < 8; j++) {
                uint32_t b0 = __float_as_uint(cs[kk * 8 + lb][j * 8 + la]);
                uint32_t b1 = __float_as_uint(cs[kk * 8 + 4 + lb][j * 8 + la]);
                mma8(acc[j], a0, a1, a2, a3, b0, b1);
            }
        }
        __syncthreads();
    }

    // ---- epilogue: BN + softmax + store + a_sum ----
    if (tid < 64) {
        float istd = rsqrtf(rv[tid] + 1e-5f);
        float s = bnw[tid] * istd;
        scf[tid] = s;
        shf[tid] = bnb[tid] - rm[tid] * s;
    }
    __syncthreads();

    float vA[8][2], vB[8][2];
#pragma unroll
    for (int j = 0; j < 8; j++)
#pragma unroll
        for (int e = 0; e < 2; e++) {
            int col = j * 8 + lb * 2 + e;
            float s = scf[col], h = shf[col];
            vA[j][e] = acc[j][e]     * s + h;
            vB[j][e] = acc[j][2 + e] * s + h;
        }

    // softmax row A (rows share lanes differing in bits 0,1)
    float mA = -1e30f, mB = -1e30f;
#pragma unroll
    for (int j = 0; j < 8; j++)
#pragma unroll
        for (int e = 0; e < 2; e++) { mA = fmaxf(mA, vA[j][e]); mB = fmaxf(mB, vB[j][e]); }
    mA = fmaxf(mA, __shfl_xor_sync(0xffffffffu, mA, 1));
    mA = fmaxf(mA, __shfl_xor_sync(0xffffffffu, mA, 2));
    mB = fmaxf(mB, __shfl_xor_sync(0xffffffffu, mB, 1));
    mB = fmaxf(mB, __shfl_xor_sync(0xffffffffu, mB, 2));
    float sA = 0.0f, sB = 0.0f;
#pragma unroll
    for (int j = 0; j < 8; j++)
#pragma unroll
        for (int e = 0; e < 2; e++) {
            vA[j][e] = __expf(vA[j][e] - mA); sA += vA[j][e];
            vB[j][e] = __expf(vB[j][e] - mB); sB += vB[j][e];
        }
    sA += __shfl_xor_sync(0xffffffffu, sA, 1);
    sA += __shfl_xor_sync(0xffffffffu, sA, 2);
    sB += __shfl_xor_sync(0xffffffffu, sB, 1);
    sB += __shfl_xor_sync(0xffffffffu, sB, 2);
    float invA = 1.0f / sA, invB = 1.0f / sB;

    float csum[8][2];
    const int grA = row0 + w * 16 + la;
    const int grB = grA + 8;
    float* ag = g_assign;
#pragma unroll
    for (int j = 0; j < 8; j++) {
#pragma unroll
        for (int e = 0; e < 2; e++) {
            vA[j][e] *= invA;
            vB[j][e] *= invB;
            csum[j][e] = vA[j][e] + vB[j][e];
        }
        *(float2*)&ag[(size_t)grA * Kk + j * 8 + lb * 2] = make_float2(vA[j][0], vA[j][1]);
        *(float2*)&ag[(size_t)grB * Kk + j * 8 + lb * 2] = make_float2(vB[j][0], vB[j][1]);
    }

    // reduce csum over the 8 row-groups of the warp (lanes differ in bits 2..4)
#pragma unroll
    for (int j = 0; j < 8; j++)
#pragma unroll
        for (int e = 0; e < 2; e++) {
            csum[j][e] += __shfl_xor_sync(0xffffffffu, csum[j][e], 4);
            csum[j][e] += __shfl_xor_sync(0xffffffffu, csum[j][e], 8);
            csum[j][e] += __shfl_xor_sync(0xffffffffu, csum[j][e], 16);
        }
    if (la == 0) {
#pragma unroll
        for (int j = 0; j < 8; j++)
#pragma unroll
            for (int e = 0; e < 2; e++)
                red[w * 64 + j * 8 + lb * 2 + e] = csum[j][e];
    }
    __syncthreads();
    if (tid < 64) {
        float s = 0.0f;
#pragma unroll
        for (int q = 0; q < 8; q++) s += red[q * 64 + tid];
        atomicAdd(&g_asum[(row0 >> 12) * Kk + tid], s);
    }
}

// ---------------------------------------------------------------------------
// k2: vlad[b,d,k] = sum_n x[b,n,d]*assign[b,n,k] via tf32 MMA.
// A = x^T (d-major, transposed on smem store), B = assign.
// Block: 128 thr (4 warps), tile d=64 x k=64, n chunk 32. Grid (8, 32).
// ---------------------------------------------------------------------------
__global__ __launch_bounds__(128) void k2_vlad(const float* __restrict__ x)
{
    __shared__ float xs[64][36];    // x^T chunk [d][n], bank = d*4+n (perfect)
    __shared__ float as[32][72];    // assign chunk [n][k], bank = n*8+k (perfect)

    const int tid  = threadIdx.x;
    const int lane = tid & 31;
    const int w    = tid >> 5;
    const int la   = lane >> 2;
    const int lb   = lane & 3;
    const int b    = blockIdx.y;
    const int d0   = blockIdx.x * 64;

    // x loader: thread -> n row (tid&31), d segment (tid>>5)*16
    const int nr = tid & 31;
    const int dc = (tid >> 5) * 16;
    // assign loader: thread -> n row tid>>2, k segment (tid&3)*16
    const int ar = tid >> 2;
    const int akc = (tid & 3) * 16;

    const float* xg = x + (size_t)b * Nn * Dd + d0;
    const float* ag = g_assign + (size_t)b * Nn * Kk;

    float acc[8][4];
#pragma unroll
    for (int j = 0; j < 8; j++)
#pragma unroll
        for (int q = 0; q < 4; q++) acc[j][q] = 0.0f;

    float4 px[4], pa[4];
#pragma unroll
    for (int q = 0; q < 4; q++) {
        px[q] = *(const float4*)&xg[(size_t)nr * Dd + dc + q * 4];
        pa[q] = *(const float4*)&ag[(size_t)ar * Kk + akc + q * 4];
    }

    for (int c = 0; c < 128; c++) {
        // store x transposed (scalar, conflict-free: bank = col*4+lane)
#pragma unroll
        for (int q = 0; q < 4; q++) {
            xs[dc + q * 4 + 0][nr] = tf32f(px[q].x);
            xs[dc + q * 4 + 1][nr] = tf32f(px[q].y);
            xs[dc + q * 4 + 2][nr] = tf32f(px[q].z);
            xs[dc + q * 4 + 3][nr] = tf32f(px[q].w);
            float4 t = make_float4(tf32f(pa[q].x), tf32f(pa[q].y),
                                   tf32f(pa[q].z), tf32f(pa[q].w));
            *(float4*)&as[ar][akc + q * 4] = t;
        }
        __syncthreads();

        if (c < 127) {
            int n0 = (c + 1) * 32;
#pragma unroll
            for (int q = 0; q < 4; q++) {
                px[q] = *(const float4*)&xg[(size_t)(n0 + nr) * Dd + dc + q * 4];
                pa[q] = *(const float4*)&ag[(size_t)(n0 + ar) * Kk + akc + q * 4];
            }
        }

        const int wr = w * 16 + la;
#pragma unroll
        for (int kk = 0; kk < 4; kk++) {
            uint32_t a0 = __float_as_uint(xs[wr][kk * 8 + lb]);
            uint32_t a1 = __float_as_uint(xs[wr + 8][kk * 8 + lb]);
            uint32_t a2 = __float_as_uint(xs[wr][kk * 8 + 4 + lb]);
            uint32_t a3 = __float_as_uint(xs[wr + 8][kk * 8 + 4 + lb]);
#pragma unroll
            for (int j = 0; j < 8; j++) {
                uint32_t b0 = __float_as_uint(as[kk * 8 + lb][j * 8 + la]);
                uint32_t b1 = __float_as_uint(as[kk * 8 + 4 + lb][j * 8 + la]);
                mma8(acc[j], a0, a1, a2, a3, b0, b1);
            }
        }
        __syncthreads();
    }

    // epilogue: scatter to g_vlad[b][k][d]
    const int gdA = d0 + w * 16 + la;
    const int gdB = gdA + 8;
#pragma unroll
    for (int j = 0; j < 8; j++)
#pragma unroll
        for (int e = 0; e < 2; e++) {
            int col = j * 8 + lb * 2 + e;
            g_vlad[((size_t)b * Kk + col) * Dd + gdA] = acc[j][e];
            g_vlad[((size_t)b * Kk + col) * Dd + gdB] = acc[j][2 + e];
        }
}

// ---------------------------------------------------------------------------
// k3: subtract a_sum*clusters2, intra-normalize over D, accumulate global sumsq
// ---------------------------------------------------------------------------
__global__ __launch_bounds__(128) void k3_colnorm(const float* __restrict__ c2,
                                                  float* __restrict__ out)
{
    const int bk = blockIdx.x;
    const int b = bk >> 6;
    const int k = bk & 63;
    const int tid = threadIdx.x;

    const float a = g_asum[bk];
    const float* vr = g_vlad + (size_t)bk * Dd;

    float v[4];
    float ss = 0.0f;
#pragma unroll
    for (int p = 0; p < 4; p++) {
        int d = tid + p * 128;
        float t = vr[d] - a * c2[(size_t)d * Kk + k];
        v[p] = t;
        ss += t * t;
    }
#pragma unroll
    for (int o = 16; o; o >>= 1) ss += __shfl_xor_sync(0xffffffffu, ss, o);

    __shared__ float sred[4];
    if ((tid & 31) == 0) sred[tid >> 5] = ss;
    __syncthreads();
    float tot = sred[0] + sred[1] + sred[2] + sred[3];
    float inv = 1.0f / fmaxf(sqrtf(tot), 1e-12f);
    if (tid == 0) atomicAdd(&g_gnormsq[b], tot * inv * inv);

    float* ob = out + (size_t)b * (Dd * Kk);
#pragma unroll
    for (int p = 0; p < 4; p++) {
        int d = tid + p * 128;
        ob[(size_t)d * Kk + k] = v[p] * inv;
    }
}

// ---------------------------------------------------------------------------
__global__ void k4_scale(float* __restrict__ out)
{
    int idx = blockIdx.x * 256 + threadIdx.x;
    int b = idx >> 15;
    out[idx] *= 1.0f / fmaxf(sqrtf(g_gnormsq[b]), 1e-12f);
}

// ---------------------------------------------------------------------------
extern "C" void kernel_launch(void* const* d_in, const int* in_sizes, int n_in,
                              void* d_out, int out_size)
{
    const float* x        = (const float*)d_in[0];
    const float* clusters = (const float*)d_in[1];
    const float* c2       = (const float*)d_in[2];
    const float* bnw      = (const float*)d_in[3];
    const float* bnb      = (const float*)d_in[4];
    const float* rm       = (const float*)d_in[5];
    const float* rv       = (const float*)d_in[6];
    float* out = (float*)d_out;

    k0_init<<<8, 256>>>();
    k1_logits_softmax<<<(Bb * Nn) / 128, 256>>>(x, clusters, bnw, bnb, rm, rv);
    dim3 g2(Dd / 64, Bb);
    k2_vlad<<<g2, 128>>>(x);
    k3_colnorm<<<Bb * Kk, 128>>>(c2, out);
    k4_scale<<<(Bb * Dd * Kk) / 256, 256>>>(out);
}

// round 6
// speedup vs baseline: 1.9456x; 1.0025x over previous
#include <cuda_runtime.h>
#include <math.h>
#include <stdint.h>

// B=32, N=4096, D=512, K=64
#define Bb 32
#define Nn 4096
#define Dd 512
#define Kk 64

__device__ float g_assign[(size_t)Bb * Nn * Kk];   // softmax assignments [b,n,k]
__device__ float g_vlad[(size_t)Bb * Kk * Dd];     // raw vlad, stored [b,k,d]
__device__ float g_asum[Bb * Kk];
__device__ float g_gnormsq[Bb];

// ---- tf32 helpers ----------------------------------------------------------
__device__ __forceinline__ uint32_t tf32b(float f) {
    uint32_t u; asm("cvt.rna.tf32.f32 %0, %1;" : "=r"(u) : "f"(f)); return u;
}
__device__ __forceinline__ float tf32f(float f) { return __uint_as_float(tf32b(f)); }

__device__ __forceinline__ void mma8(float* c, uint32_t a0, uint32_t a1,
                                     uint32_t a2, uint32_t a3,
                                     uint32_t b0, uint32_t b1) {
    asm volatile(
        "mma.sync.aligned.m16n8k8.row.col.f32.tf32.tf32.f32 "
        "{%0,%1,%2,%3},{%4,%5,%6,%7},{%8,%9},{%0,%1,%2,%3};\n"
        : "+f"(c[0]), "+f"(c[1]), "+f"(c[2]), "+f"(c[3])
        : "r"(a0), "r"(a1), "r"(a2), "r"(a3), "r"(b0), "r"(b1));
}

// ---------------------------------------------------------------------------
__global__ void k0_init() {
    int i = blockIdx.x * 256 + threadIdx.x;
    if (i < Bb * Kk) g_asum[i] = 0.0f;
    if (i < Bb)      g_gnormsq[i] = 0.0f;
}

// ---------------------------------------------------------------------------
// k1: logits = x @ clusters (131072x512 @ 512x64) via tf32 MMA, fused
// BN(eval) + softmax + assignment store + a_sum atomic.
// Block: 256 thr (8 warps), tile 128 rows x 64 cols, K chunk 32.
// Warp w owns rows w*16..w*16+15, all 64 cols (8 n-tiles of m16n8k8).
// ---------------------------------------------------------------------------
__global__ __launch_bounds__(256) void k1_logits_softmax(
    const float* __restrict__ x,
    const float* __restrict__ clusters,
    const float* __restrict__ bnw,
    const float* __restrict__ bnb,
    const float* __restrict__ rm,
    const float* __restrict__ rv)
{
    __shared__ float xs[128][36];   // x chunk [row][k], bank = row*4+k (perfect)
    __shared__ float cs[32][72];    // clusters chunk [k][n], bank = k*8+n (perfect)
    __shared__ float scf[64], shf[64];
    __shared__ float red[8 * 64];

    const int tid  = threadIdx.x;
    const int lane = tid & 31;
    const int w    = tid >> 5;
    const int la   = lane >> 2;     // 0..7
    const int lb   = lane & 3;      // 0..3
    const int row0 = blockIdx.x * 128;

    // loader mappings
    const int xr = tid >> 1;              // 0..127
    const int xc = (tid & 1) * 16;        // 0 or 16
    const int cr = tid >> 3;              // 0..31
    const int cc = (tid & 7) * 8;         // 0..56

    const float* xg = x + (size_t)row0 * Dd;

    float acc[8][4];
#pragma unroll
    for (int j = 0; j < 8; j++)
#pragma unroll
        for (int q = 0; q < 4; q++) acc[j][q] = 0.0f;

    float4 px[4];
    float4 pc[2];
#pragma unroll
    for (int q = 0; q < 4; q++)
        px[q] = *(const float4*)&xg[(size_t)xr * Dd + xc + q * 4];
#pragma unroll
    for (int q = 0; q < 2; q++)
        pc[q] = *(const float4*)&clusters[(size_t)cr * Kk + cc + q * 4];

    for (int c = 0; c < 16; c++) {
        // store prefetched chunk (convert to tf32 bits)
#pragma unroll
        for (int q = 0; q < 4; q++) {
            float4 t = make_float4(tf32f(px[q].x), tf32f(px[q].y),
                                   tf32f(px[q].z), tf32f(px[q].w));
            *(float4*)&xs[xr][xc + q * 4] = t;
        }
#pragma unroll
        for (int q = 0; q < 2; q++) {
            float4 t = make_float4(tf32f(pc[q].x), tf32f(pc[q].y),
                                   tf32f(pc[q].z), tf32f(pc[q].w));
            *(float4*)&cs[cr][cc + q * 4] = t;
        }
        __syncthreads();

        if (c < 15) {
            int d0 = (c + 1) * 32;
#pragma unroll
            for (int q = 0; q < 4; q++)
                px[q] = *(const float4*)&xg[(size_t)xr * Dd + d0 + xc + q * 4];
#pragma unroll
            for (int q = 0; q < 2; q++)
                pc[q] = *(const float4*)&clusters[(size_t)(d0 + cr) * Kk + cc + q * 4];
        }

        const int wr = w * 16 + la;
#pragma unroll
        for (int kk = 0; kk < 4; kk++) {
            uint32_t a0 = __float_as_uint(xs[wr][kk * 8 + lb]);
            uint32_t a1 = __float_as_uint(xs[wr + 8][kk * 8 + lb]);
            uint32_t a2 = __float_as_uint(xs[wr][kk * 8 + 4 + lb]);
            uint32_t a3 = __float_as_uint(xs[wr + 8][kk * 8 + 4 + lb]);
#pragma unroll
            for (int j = 0; j < 8; j++) {
                uint32_t b0 = __float_as_uint(cs[kk * 8 + lb][j * 8 + la]);
                uint32_t b1 = __float_as_uint(cs[kk * 8 + 4 + lb][j * 8 + la]);
                mma8(acc[j], a0, a1, a2, a3, b0, b1);
            }
        }
        __syncthreads();
    }

    // ---- epilogue: BN + softmax + store + a_sum ----
    if (tid < 64) {
        float istd = rsqrtf(rv[tid] + 1e-5f);
        float s = bnw[tid] * istd;
        scf[tid] = s;
        shf[tid] = bnb[tid] - rm[tid] * s;
    }
    __syncthreads();

    float vA[8][2], vB[8][2];
#pragma unroll
    for (int j = 0; j < 8; j++)
#pragma unroll
        for (int e = 0; e < 2; e++) {
            int col = j * 8 + lb * 2 + e;
            float s = scf[col], h = shf[col];
            vA[j][e] = acc[j][e]     * s + h;
            vB[j][e] = acc[j][2 + e] * s + h;
        }

    // softmax row A (rows share lanes differing in bits 0,1)
    float mA = -1e30f, mB = -1e30f;
#pragma unroll
    for (int j = 0; j < 8; j++)
#pragma unroll
        for (int e = 0; e < 2; e++) { mA = fmaxf(mA, vA[j][e]); mB = fmaxf(mB, vB[j][e]); }
    mA = fmaxf(mA, __shfl_xor_sync(0xffffffffu, mA, 1));
    mA = fmaxf(mA, __shfl_xor_sync(0xffffffffu, mA, 2));
    mB = fmaxf(mB, __shfl_xor_sync(0xffffffffu, mB, 1));
    mB = fmaxf(mB, __shfl_xor_sync(0xffffffffu, mB, 2));
    float sA = 0.0f, sB = 0.0f;
#pragma unroll
    for (int j = 0; j < 8; j++)
#pragma unroll
        for (int e = 0; e < 2; e++) {
            vA[j][e] = __expf(vA[j][e] - mA); sA += vA[j][e];
            vB[j][e] = __expf(vB[j][e] - mB); sB += vB[j][e];
        }
    sA += __shfl_xor_sync(0xffffffffu, sA, 1);
    sA += __shfl_xor_sync(0xffffffffu, sA, 2);
    sB += __shfl_xor_sync(0xffffffffu, sB, 1);
    sB += __shfl_xor_sync(0xffffffffu, sB, 2);
    float invA = 1.0f / sA, invB = 1.0f / sB;

    float csum[8][2];
    const int grA = row0 + w * 16 + la;
    const int grB = grA + 8;
    float* ag = g_assign;
#pragma unroll
    for (int j = 0; j < 8; j++) {
#pragma unroll
        for (int e = 0; e < 2; e++) {
            vA[j][e] *= invA;
            vB[j][e] *= invB;
            csum[j][e] = vA[j][e] + vB[j][e];
        }
        *(float2*)&ag[(size_t)grA * Kk + j * 8 + lb * 2] = make_float2(vA[j][0], vA[j][1]);
        *(float2*)&ag[(size_t)grB * Kk + j * 8 + lb * 2] = make_float2(vB[j][0], vB[j][1]);
    }

    // reduce csum over the 8 row-groups of the warp (lanes differ in bits 2..4)
#pragma unroll
    for (int j = 0; j < 8; j++)
#pragma unroll
        for (int e = 0; e < 2; e++) {
            csum[j][e] += __shfl_xor_sync(0xffffffffu, csum[j][e], 4);
            csum[j][e] += __shfl_xor_sync(0xffffffffu, csum[j][e], 8);
            csum[j][e] += __shfl_xor_sync(0xffffffffu, csum[j][e], 16);
        }
    if (la == 0) {
#pragma unroll
        for (int j = 0; j < 8; j++)
#pragma unroll
            for (int e = 0; e < 2; e++)
                red[w * 64 + j * 8 + lb * 2 + e] = csum[j][e];
    }
    __syncthreads();
    if (tid < 64) {
        float s = 0.0f;
#pragma unroll
        for (int q = 0; q < 8; q++) s += red[q * 64 + tid];
        atomicAdd(&g_asum[(row0 >> 12) * Kk + tid], s);
    }
}

// ---------------------------------------------------------------------------
// k2: vlad[b,d,k] = sum_n x[b,n,d]*assign[b,n,k] via tf32 MMA.
// A = x^T (d-major, transposed on smem store), B = assign.
// Block: 128 thr (4 warps), tile d=64 x k=64, n chunk 32. Grid (8, 32).
// ---------------------------------------------------------------------------
__global__ __launch_bounds__(128) void k2_vlad(const float* __restrict__ x)
{
    __shared__ float xs[64][36];    // x^T chunk [d][n], bank = d*4+n (perfect)
    __shared__ float as[32][72];    // assign chunk [n][k], bank = n*8+k (perfect)

    const int tid  = threadIdx.x;
    const int lane = tid & 31;
    const int w    = tid >> 5;
    const int la   = lane >> 2;
    const int lb   = lane & 3;
    const int b    = blockIdx.y;
    const int d0   = blockIdx.x * 64;

    // x loader: thread -> n row (tid&31), d segment (tid>>5)*16
    const int nr = tid & 31;
    const int dc = (tid >> 5) * 16;
    // assign loader: thread -> n row tid>>2, k segment (tid&3)*16
    const int ar = tid >> 2;
    const int akc = (tid & 3) * 16;

    const float* xg = x + (size_t)b * Nn * Dd + d0;
    const float* ag = g_assign + (size_t)b * Nn * Kk;

    float acc[8][4];
#pragma unroll
    for (int j = 0; j < 8; j++)
#pragma unroll
        for (int q = 0; q < 4; q++) acc[j][q] = 0.0f;

    float4 px[4], pa[4];
#pragma unroll
    for (int q = 0; q < 4; q++) {
        px[q] = *(const float4*)&xg[(size_t)nr * Dd + dc + q * 4];
        pa[q] = *(const float4*)&ag[(size_t)ar * Kk + akc + q * 4];
    }

    for (int c = 0; c < 128; c++) {
        // store x transposed (scalar, conflict-free: bank = col*4+lane)
#pragma unroll
        for (int q = 0; q < 4; q++) {
            xs[dc + q * 4 + 0][nr] = tf32f(px[q].x);
            xs[dc + q * 4 + 1][nr] = tf32f(px[q].y);
            xs[dc + q * 4 + 2][nr] = tf32f(px[q].z);
            xs[dc + q * 4 + 3][nr] = tf32f(px[q].w);
            float4 t = make_float4(tf32f(pa[q].x), tf32f(pa[q].y),
                                   tf32f(pa[q].z), tf32f(pa[q].w));
            *(float4*)&as[ar][akc + q * 4] = t;
        }
        __syncthreads();

        if (c < 127) {
            int n0 = (c + 1) * 32;
#pragma unroll
            for (int q = 0; q < 4; q++) {
                px[q] = *(const float4*)&xg[(size_t)(n0 + nr) * Dd + dc + q * 4];
                pa[q] = *(const float4*)&ag[(size_t)(n0 + ar) * Kk + akc + q * 4];
            }
        }

        const int wr = w * 16 + la;
#pragma unroll
        for (int kk = 0; kk < 4; kk++) {
            uint32_t a0 = __float_as_uint(xs[wr][kk * 8 + lb]);
            uint32_t a1 = __float_as_uint(xs[wr + 8][kk * 8 + lb]);
            uint32_t a2 = __float_as_uint(xs[wr][kk * 8 + 4 + lb]);
            uint32_t a3 = __float_as_uint(xs[wr + 8][kk * 8 + 4 + lb]);
#pragma unroll
            for (int j = 0; j < 8; j++) {
                uint32_t b0 = __float_as_uint(as[kk * 8 + lb][j * 8 + la]);
                uint32_t b1 = __float_as_uint(as[kk * 8 + 4 + lb][j * 8 + la]);
                mma8(acc[j], a0, a1, a2, a3, b0, b1);
            }
        }
        __syncthreads();
    }

    // epilogue: scatter to g_vlad[b][k][d]
    const int gdA = d0 + w * 16 + la;
    const int gdB = gdA + 8;
#pragma unroll
    for (int j = 0; j < 8; j++)
#pragma unroll
        for (int e = 0; e < 2; e++) {
            int col = j * 8 + lb * 2 + e;
            g_vlad[((size_t)b * Kk + col) * Dd + gdA] = acc[j][e];
            g_vlad[((size_t)b * Kk + col) * Dd + gdB] = acc[j][2 + e];
        }
}

// ---------------------------------------------------------------------------
// k3: subtract a_sum*clusters2, intra-normalize over D, accumulate global sumsq
// ---------------------------------------------------------------------------
__global__ __launch_bounds__(128) void k3_colnorm(const float* __restrict__ c2,
                                                  float* __restrict__ out)
{
    const int bk = blockIdx.x;
    const int b = bk >> 6;
    const int k = bk & 63;
    const int tid = threadIdx.x;

    const float a = g_asum[bk];
    const float* vr = g_vlad + (size_t)bk * Dd;

    float v[4];
    float ss = 0.0f;
#pragma unroll
    for (int p = 0; p < 4; p++) {
        int d = tid + p * 128;
        float t = vr[d] - a * c2[(size_t)d * Kk + k];
        v[p] = t;
        ss += t * t;
    }
#pragma unroll
    for (int o = 16; o; o >>= 1) ss += __shfl_xor_sync(0xffffffffu, ss, o);

    __shared__ float sred[4];
    if ((tid & 31) == 0) sred[tid >> 5] = ss;
    __syncthreads();
    float tot = sred[0] + sred[1] + sred[2] + sred[3];
    float inv = 1.0f / fmaxf(sqrtf(tot), 1e-12f);
    if (tid == 0) atomicAdd(&g_gnormsq[b], tot * inv * inv);

    float* ob = out + (size_t)b * (Dd * Kk);
#pragma unroll
    for (int p = 0; p < 4; p++) {
        int d = tid + p * 128;
        ob[(size_t)d * Kk + k] = v[p] * inv;
    }
}

// ---------------------------------------------------------------------------
__global__ void k4_scale(float* __restrict__ out)
{
    int idx = blockIdx.x * 256 + threadIdx.x;
    int b = idx >> 15;
    out[idx] *= 1.0f / fmaxf(sqrtf(g_gnormsq[b]), 1e-12f);
}

// ---------------------------------------------------------------------------
extern "C" void kernel_launch(void* const* d_in, const int* in_sizes, int n_in,
                              void* d_out, int out_size)
{
    const float* x        = (const float*)d_in[0];
    const float* clusters = (const float*)d_in[1];
    const float* c2       = (const float*)d_in[2];
    const float* bnw      = (const float*)d_in[3];
    const float* bnb      = (const float*)d_in[4];
    const float* rm       = (const float*)d_in[5];
    const float* rv       = (const float*)d_in[6];
    float* out = (float*)d_out;

    k0_init<<<8, 256>>>();
    k1_logits_softmax<<<(Bb * Nn) / 128, 256>>>(x, clusters, bnw, bnb, rm, rv);
    dim3 g2(Dd / 64, Bb);
    k2_vlad<<<g2, 128>>>(x);
    k3_colnorm<<<Bb * Kk, 128>>>(c2, out);
    k4_scale<<<(Bb * Dd * Kk) / 256, 256>>>(out);
}